// round 16
// baseline (speedup 1.0000x reference)
#include <cuda_runtime.h>
#include <math.h>
#include <stdint.h>

// ---------------- problem constants ----------------
#define NPIX   262144            // 512*512 pixels per image
#define NIMG   64
#define NIC    128               // image-channels: [0,64)=region, [64,128)=affinity
#define NTHREADS 256
#define POS_THR 0.1f
#define FALLBACK_POS 1000.0f

// ---------------- k1b TMA pipeline geometry ----------------
#define K1B_BPI   16                         // blocks per image
#define K1B_GRID  (NIMG * K1B_BPI)           // 1024
#define BLK_PX    (NPIX / K1B_BPI)           // 16384 pixels per block
#define STAGE_PX  1024                       // pixels per pipeline stage
#define NSTAGES   (BLK_PX / STAGE_PX)        // 16
#define NBUF      3                          // ring depth
#define STAGE_ARR_BYTES (STAGE_PX * 4)       // 4096 B per array per stage
#define STAGE_BYTES (5 * STAGE_ARR_BYTES)    // 20480 B per stage
#define DYN_SMEM  (NBUF * STAGE_BYTES)       // 61440 B -> 3 CTAs/SM

// ---------------- k1a sampling ----------------
#define SRATE   64                           // 4096 samples per IC
#define NBINS   1024
#define QBIN    (1.1f / (float)NBINS)

// ---------------- device state (static, zero-initialized, allocation-free) ----
// statics are zero at module load (correct for call #1); the k1b completion block
// re-zeros everything it consumes, so later calls / graph replays stay correct.
__device__ float g_thr[NIC];    // float loss threshold per IC
__device__ float g_rho[NIC];    // local rank density dC/dv at thr
__device__ float g_p[NIC];      // positive count (exact integer-valued)
__device__ float g_ps[NIC];     // sum of loss over positives
__device__ float g_ts[NIC];     // total loss sum
__device__ float g_S[NIC];      // sum of neg losses > t
__device__ float g_C[NIC];      // count of neg losses > t (integer-valued)
__device__ unsigned g_done;     // k1b completion counter

// ---------------- helpers ----------------
__device__ __forceinline__ float warp_sum(float v) {
    #pragma unroll
    for (int o = 16; o; o >>= 1) v += __shfl_xor_sync(0xffffffffu, v, o);
    return v;
}
__device__ __forceinline__ int warp_sum_i(int v) {
    #pragma unroll
    for (int o = 16; o; o >>= 1) v += __shfl_xor_sync(0xffffffffu, v, o);
    return v;
}
__device__ __forceinline__ uint32_t smem_u32(const void* p) {
    uint32_t a;
    asm("{ .reg .u64 t; cvta.to.shared.u64 t, %1; cvt.u32.u64 %0, t; }"
        : "=r"(a) : "l"(p));
    return a;
}
__device__ __forceinline__ void mbar_init(uint32_t mbar, uint32_t cnt) {
    asm volatile("mbarrier.init.shared.b64 [%0], %1;" :: "r"(mbar), "r"(cnt) : "memory");
}
__device__ __forceinline__ void mbar_expect_tx(uint32_t mbar, uint32_t bytes) {
    asm volatile("mbarrier.arrive.expect_tx.shared.b64 _, [%0], %1;"
                 :: "r"(mbar), "r"(bytes) : "memory");
}
__device__ __forceinline__ void mbar_wait(uint32_t mbar, uint32_t parity) {
    asm volatile(
        "{\n\t.reg .pred p;\n\t"
        "WAIT_%=:\n\t"
        "mbarrier.try_wait.parity.acquire.cta.shared::cta.b64 p, [%0], %1;\n\t"
        "@p bra.uni DONE_%=;\n\t"
        "bra.uni WAIT_%=;\n\t"
        "DONE_%=:\n\t}"
        :: "r"(mbar), "r"(parity) : "memory");
}
__device__ __forceinline__ void bulk_copy(uint32_t smem_dst, const void* gmem_src,
                                          uint32_t bytes, uint32_t mbar) {
    asm volatile(
        "cp.async.bulk.shared::cta.global.mbarrier::complete_tx::bytes [%0], [%1], %2, [%3];"
        :: "r"(smem_dst), "l"(gmem_src), "r"(bytes), "r"(mbar) : "memory");
}

// ---------------- k1a: one block per image-CHANNEL -----------------------------
// 128 blocks; each loads only its channel's 3 arrays: 4 strided regions x 1024
// float4 -> 4096 samples, SMEM histogram, in-block scan for threshold + rho.
__global__ void __launch_bounds__(NTHREADS) k1a_thresh(
    const float* __restrict__ rlab, const float* __restrict__ alab,
    const float* __restrict__ rpre, const float* __restrict__ apre,
    const float* __restrict__ mask, const int* __restrict__ neg_rto)
{
    const int ic  = blockIdx.x;
    const int img = ic & (NIMG - 1);
    const int ch  = ic >> 6;
    const float* __restrict__ lab = ch ? alab : rlab;
    const float* __restrict__ pre = ch ? apre : rpre;
    const size_t ibase = (size_t)img * NPIX;
    const int tid = threadIdx.x;
    const int ln  = tid & 31, w = tid >> 5;

    __shared__ int hist[NBINS];
    #pragma unroll
    for (int i = tid; i < NBINS; i += NTHREADS) hist[i] = 0;
    __syncthreads();

    int posc = 0;
    #pragma unroll
    for (int c = 0; c < 4; ++c) {
        const size_t off = ibase + (size_t)c * (NPIX / 4) + (size_t)tid * 4;
        float4 L = __ldcs((const float4*)(lab + off));
        float4 P = __ldcs((const float4*)(pre + off));
        float4 M = __ldcs((const float4*)(mask + off));

        #define SPROC(LL, PP, MM)                                      \
        {   float d = (PP) - (LL);                                     \
            float l = d * d * (MM);                                    \
            bool po = (LL) > POS_THR;                                  \
            posc += po ? 1 : 0;                                        \
            if (!po) {                                                 \
                int cc = __float2int_rz(sqrtf(l) * ((float)NBINS / 1.1f)); \
                atomicAdd(&hist[min(cc, NBINS - 1)], 1);               \
            } }
        SPROC(L.x, P.x, M.x)
        SPROC(L.y, P.y, M.y)
        SPROC(L.z, P.z, M.z)
        SPROC(L.w, P.w, M.w)
        #undef SPROC
    }

    // reduce sampled positive count
    __shared__ int shp[NTHREADS / 32];
    {
        int pw = warp_sum_i(posc);
        if (ln == 0) shp[w] = pw;
    }
    __syncthreads();
    __shared__ float s_j;
    __shared__ int s_total, s_bstar;
    __shared__ int wtot[NTHREADS / 32];
    if (tid == 0) {
        int ps = 0;
        #pragma unroll
        for (int i = 0; i < NTHREADS / 32; ++i) ps += shp[i];
        float peff_s = (ps > 0) ? (float)ps : (FALLBACK_POS / (float)SRATE);
        s_j = (float)(*neg_rto) * peff_s;
        s_bstar = NBINS - 1;
    }
    __syncthreads();

    int h0 = hist[4 * tid + 0];
    int h1 = hist[4 * tid + 1];
    int h2 = hist[4 * tid + 2];
    int h3 = hist[4 * tid + 3];
    int csum = h0 + h1 + h2 + h3;

    int x = csum;
    #pragma unroll
    for (int o = 1; o < 32; o <<= 1) {
        int y = __shfl_up_sync(0xffffffffu, x, o);
        if (ln >= o) x += y;
    }
    if (ln == 31) wtot[w] = x;
    __syncthreads();
    int woff = 0;
    #pragma unroll
    for (int i = 0; i < NTHREADS / 32; ++i) woff += (i < w) ? wtot[i] : 0;
    if (tid == 0) {
        int tot = 0;
        #pragma unroll
        for (int i = 0; i < NTHREADS / 32; ++i) tot += wtot[i];
        s_total = tot;
    }
    __syncthreads();

    {
        const int total = s_total;
        const float j = s_j;
        int run = (x - csum) + woff;   // exclusive prefix: sum of bins < 4*tid
        int b = -1;
        run += h0; if ((float)(total - run) <= j) { b = 4 * tid + 0; }
        if (b < 0) { run += h1; if ((float)(total - run) <= j) b = 4 * tid + 1; }
        if (b < 0) { run += h2; if ((float)(total - run) <= j) b = 4 * tid + 2; }
        if (b < 0) { run += h3; if ((float)(total - run) <= j) b = 4 * tid + 3; }
        if (b >= 0) atomicMin(&s_bstar, b);
    }
    __syncthreads();

    if (tid == 0) {
        const int b = s_bstar;
        const float t1 = ((float)(b + 1) * QBIN) * ((float)(b + 1) * QBIN);
        g_thr[ic] = t1;
        const int blo = max(b - 8, 0);
        const int bhi = min(b + 8, NBINS - 1);
        int wcnt = 0;
        for (int c = blo; c <= bhi; ++c) wcnt += hist[c];
        const float vlo = ((float)blo * QBIN) * ((float)blo * QBIN);
        const float vhi = ((float)(bhi + 1) * QBIN) * ((float)(bhi + 1) * QBIN);
        const float dv  = fmaxf(vhi - vlo, 1e-12f);
        g_rho[ic] = (wcnt > 0) ? ((float)SRATE * (float)wcnt / dv) : 3.4e38f;
    }
}

// ---------------- k1b: 3-buffer bulk-async pipelined streaming pass ------------
__global__ void __launch_bounds__(NTHREADS) k1b_scan(
    const float* __restrict__ rlab, const float* __restrict__ alab,
    const float* __restrict__ rpre, const float* __restrict__ apre,
    const float* __restrict__ mask, const int* __restrict__ neg_rto,
    float* __restrict__ out)
{
    extern __shared__ __align__(128) unsigned char dsm[];
    __shared__ unsigned long long mbar_full[NBUF];

    const int blk   = blockIdx.x;
    const int img   = blk / K1B_BPI;
    const int chunk = blk % K1B_BPI;
    const size_t pxbase = (size_t)img * NPIX + (size_t)chunk * BLK_PX;
    const int tid = threadIdx.x;
    const int w = tid >> 5, ln = tid & 31;

    const float* arrs[5];
    arrs[0] = rlab; arrs[1] = rpre; arrs[2] = alab; arrs[3] = apre; arrs[4] = mask;

    uint32_t mb[NBUF];
    #pragma unroll
    for (int i = 0; i < NBUF; ++i) mb[i] = smem_u32(&mbar_full[i]);
    const uint32_t dbase = smem_u32(dsm);

    if (tid == 0) {
        #pragma unroll
        for (int i = 0; i < NBUF; ++i) mbar_init(mb[i], 1);
        asm volatile("fence.proxy.async;" ::: "memory");
    }
    __syncthreads();

    // prologue: fill NBUF-1 buffers
    if (tid == 0) {
        #pragma unroll
        for (int s = 0; s < NBUF - 1; ++s) {
            mbar_expect_tx(mb[s], STAGE_BYTES);
            #pragma unroll
            for (int a = 0; a < 5; ++a) {
                const char* src = (const char*)arrs[a] +
                                  (pxbase + (size_t)s * STAGE_PX) * 4;
                bulk_copy(dbase + s * STAGE_BYTES + a * STAGE_ARR_BYTES,
                          src, STAGE_ARR_BYTES, mb[s]);
            }
        }
    }

    const float t_r = g_thr[img];
    const float t_a = g_thr[NIMG + img];

    // packed int accumulators: p in bits[16:], C in bits[:16] (max 64 each/thread)
    int   pc_r = 0, pc_a = 0;
    float ps_r = 0.f, ts_r = 0.f, S_r = 0.f;
    float ps_a = 0.f, ts_a = 0.f, S_a = 0.f;

    int buf = 0, phase = 0;       // stage s -> buffer s%NBUF, parity (s/NBUF)&1
    for (int s = 0; s < NSTAGES; ++s) {
        mbar_wait(mb[buf], (unsigned)phase);

        const unsigned char* sb = dsm + buf * STAGE_BYTES;
        const float4* RL = (const float4*)(sb + 0 * STAGE_ARR_BYTES);
        const float4* RP = (const float4*)(sb + 1 * STAGE_ARR_BYTES);
        const float4* AL = (const float4*)(sb + 2 * STAGE_ARR_BYTES);
        const float4* AP = (const float4*)(sb + 3 * STAGE_ARR_BYTES);
        const float4* MK = (const float4*)(sb + 4 * STAGE_ARR_BYTES);

        // 256 float4 per stage -> one per thread
        float4 rl = RL[tid], rp = RP[tid], al = AL[tid], ap = AP[tid], mk = MK[tid];

        #define PROC(L, P, M, T, PC, PS, TS, SS)                   \
        {   float d = (P) - (L);                                   \
            float l = d * d * (M);                                 \
            TS += l;                                               \
            bool po = (L) > POS_THR;                               \
            PS += po ? l : 0.f;                                    \
            bool sel = (!po) && (l > (T));                         \
            SS += sel ? l : 0.f;                                   \
            PC += (po ? 0x10000 : 0) + (sel ? 1 : 0); }

        PROC(rl.x, rp.x, mk.x, t_r, pc_r, ps_r, ts_r, S_r)
        PROC(rl.y, rp.y, mk.y, t_r, pc_r, ps_r, ts_r, S_r)
        PROC(rl.z, rp.z, mk.z, t_r, pc_r, ps_r, ts_r, S_r)
        PROC(rl.w, rp.w, mk.w, t_r, pc_r, ps_r, ts_r, S_r)
        PROC(al.x, ap.x, mk.x, t_a, pc_a, ps_a, ts_a, S_a)
        PROC(al.y, ap.y, mk.y, t_a, pc_a, ps_a, ts_a, S_a)
        PROC(al.z, ap.z, mk.z, t_a, pc_a, ps_a, ts_a, S_a)
        PROC(al.w, ap.w, mk.w, t_a, pc_a, ps_a, ts_a, S_a)
        #undef PROC

        __syncthreads();   // buffer fully consumed by all threads
        const int snew = s + NBUF - 1;
        if (tid == 0 && snew < NSTAGES) {
            const int nb = snew % NBUF;
            mbar_expect_tx(mb[nb], STAGE_BYTES);
            #pragma unroll
            for (int a = 0; a < 5; ++a) {
                const char* src = (const char*)arrs[a] +
                                  (pxbase + (size_t)snew * STAGE_PX) * 4;
                bulk_copy(dbase + nb * STAGE_BYTES + a * STAGE_ARR_BYTES,
                          src, STAGE_ARR_BYTES, mb[nb]);
            }
        }
        if (++buf == NBUF) { buf = 0; phase ^= 1; }
    }

    // block-reduce: 2 packed ints + 6 floats -> atomicAdd to 10 stat slots
    __shared__ int   shi[2][NTHREADS / 32];
    __shared__ float shf[6][NTHREADS / 32];
    {
        int iv[2] = {pc_r, pc_a};
        float fv[6] = {ps_r, ts_r, S_r, ps_a, ts_a, S_a};
        #pragma unroll
        for (int s = 0; s < 2; ++s) {
            int v = warp_sum_i(iv[s]);
            if (ln == 0) shi[s][w] = v;
        }
        #pragma unroll
        for (int s = 0; s < 6; ++s) {
            float v = warp_sum(fv[s]);
            if (ln == 0) shf[s][w] = v;
        }
    }
    __syncthreads();
    if (tid < 10) {
        const int ch = tid / 5;                    // 0: region, 1: affinity
        const int s  = tid % 5;                    // 0:p 1:ps 2:ts 3:S 4:C
        const int ic = img + ch * NIMG;
        float v;
        if (s == 0 || s == 4) {
            int tot = 0;
            #pragma unroll
            for (int i = 0; i < NTHREADS / 32; ++i) tot += shi[ch][i];
            v = (s == 0) ? (float)(tot >> 16) : (float)(tot & 0xffff);
        } else {
            const int f = ch * 3 + (s - 1);
            float t = 0.f;
            #pragma unroll
            for (int i = 0; i < NTHREADS / 32; ++i) t += shf[f][i];
            v = t;
        }
        float* tgt;
        switch (s) {
            case 0: tgt = &g_p [ic]; break;
            case 1: tgt = &g_ps[ic]; break;
            case 2: tgt = &g_ts[ic]; break;
            case 3: tgt = &g_S [ic]; break;
            default:tgt = &g_C [ic]; break;
        }
        atomicAdd(tgt, v);
    }

    // completion detection
    __shared__ unsigned s_rank;
    __syncthreads();
    if (tid == 0) {
        __threadfence();
        s_rank = atomicAdd(&g_done, 1u);
    }
    __syncthreads();
    if (s_rank != K1B_GRID - 1) return;

    // ===== completion block: assemble final scalar, re-zero state =====
    __threadfence();
    const int t = tid;
    float v = 0.f;
    if (t < NIC) {
        const float p   = *(volatile float*)&g_p[t];
        const float ps  = *(volatile float*)&g_ps[t];
        const float ts  = *(volatile float*)&g_ts[t];
        const float S   = *(volatile float*)&g_S[t];
        const float C   = *(volatile float*)&g_C[t];
        const float th  = g_thr[t];
        const float rho = g_rho[t];
        const float n   = (float)NPIX - p;

        const float pos_loss = (p > 0.f) ? ps / fmaxf(p, 1.f) : 0.f;
        const float peff = (p > 0.f) ? p : FALLBACK_POS;
        const float kf   = (float)(*neg_rto) * peff;
        const float k    = floorf(kf);

        float neg_loss;
        if ((p > 0.f) && (n < kf)) {
            neg_loss = (ts - ps) / fmaxf(n, 1.f);
        } else {
            // top-k sum with quadratic rank-error correction:
            //   sum = S + (k-C)*t - (k-C)^2 / (2*rho)
            const float dk   = k - C;
            const float corr = (rho > 0.f) ? (dk * dk) / (2.f * rho) : 0.f;
            const float topk = fmaxf(S + dk * th - corr, 0.f);
            neg_loss = topk / kf;
        }
        v = pos_loss + neg_loss;

        // re-zero all consumed accumulators for the next invocation / replay
        g_p[t] = 0.f; g_ps[t] = 0.f; g_ts[t] = 0.f;
        g_S[t] = 0.f; g_C[t]  = 0.f;
    }
    if (t == 0) g_done = 0u;

    float* red = (float*)dsm;   // reuse pipeline smem for the final reduction
    if (t < NIC) red[t] = v;
    __syncthreads();
    #pragma unroll
    for (int o = NIC / 2; o >= 1; o >>= 1) {
        if (t < o) red[t] += red[t + o];
        __syncthreads();
    }
    if (t == 0) out[0] = red[0] / (float)NIMG;
}

// ---------------- launch ----------------
extern "C" void kernel_launch(void* const* d_in, const int* in_sizes, int n_in,
                              void* d_out, int out_size)
{
    const float* rlab = (const float*)d_in[0];
    const float* alab = (const float*)d_in[1];
    const float* rpre = (const float*)d_in[2];
    const float* apre = (const float*)d_in[3];
    const float* mask = (const float*)d_in[4];
    const int*   nrto = (const int*)  d_in[5];
    float* out = (float*)d_out;
    (void)in_sizes; (void)n_in; (void)out_size;

    cudaFuncSetAttribute(k1b_scan, cudaFuncAttributeMaxDynamicSharedMemorySize, DYN_SMEM);

    k1a_thresh<<<NIC, NTHREADS>>>(rlab, alab, rpre, apre, mask, nrto);
    k1b_scan  <<<K1B_GRID, NTHREADS, DYN_SMEM>>>(rlab, alab, rpre, apre, mask, nrto, out);
}

// round 17
// speedup vs baseline: 1.0579x; 1.0579x over previous
#include <cuda_runtime.h>
#include <math.h>
#include <stdint.h>

// ---------------- problem constants ----------------
#define NPIX   262144            // 512*512 pixels per image
#define NIMG   64
#define NIC    128               // image-channels: [0,64)=region, [64,128)=affinity
#define NTHREADS 256
#define POS_THR 0.1f
#define FALLBACK_POS 1000.0f

// ---------------- k1b TMA pipeline geometry (R15 champion) ----------------
#define K1B_BPI   16                         // blocks per image
#define K1B_GRID  (NIMG * K1B_BPI)           // 1024
#define BLK_PX    (NPIX / K1B_BPI)           // 16384 pixels per block
#define STAGE_PX  2048                       // pixels per pipeline stage
#define NSTAGES   (BLK_PX / STAGE_PX)        // 8
#define STAGE_ARR_BYTES (STAGE_PX * 4)       // 8192 B per array per stage
#define STAGE_BYTES (5 * STAGE_ARR_BYTES)    // 40960 B per stage
#define DYN_SMEM  (2 * STAGE_BYTES)          // 81920 B double buffer -> 2 CTAs/SM

// ---------------- k1a sampling (R16 per-channel champion) ----------------
#define SRATE   64                           // 4096 samples per IC
#define NBINS   1024
#define QBIN    (1.1f / (float)NBINS)

// ---------------- device state (static, zero-initialized, allocation-free) ----
// statics are zero at module load (correct for call #1); the k1b completion block
// re-zeros everything it consumes, so later calls / graph replays stay correct.
__device__ float g_thr[NIC];    // float loss threshold per IC
__device__ float g_rho[NIC];    // local rank density dC/dv at thr
__device__ float g_p[NIC];      // positive count (exact integer-valued)
__device__ float g_ps[NIC];     // sum of loss over positives
__device__ float g_ts[NIC];     // total loss sum
__device__ float g_S[NIC];      // sum of neg losses > t
__device__ float g_C[NIC];      // count of neg losses > t (integer-valued)
__device__ unsigned g_done;     // k1b completion counter

// ---------------- helpers ----------------
__device__ __forceinline__ float warp_sum(float v) {
    #pragma unroll
    for (int o = 16; o; o >>= 1) v += __shfl_xor_sync(0xffffffffu, v, o);
    return v;
}
__device__ __forceinline__ int warp_sum_i(int v) {
    #pragma unroll
    for (int o = 16; o; o >>= 1) v += __shfl_xor_sync(0xffffffffu, v, o);
    return v;
}
__device__ __forceinline__ uint32_t smem_u32(const void* p) {
    uint32_t a;
    asm("{ .reg .u64 t; cvta.to.shared.u64 t, %1; cvt.u32.u64 %0, t; }"
        : "=r"(a) : "l"(p));
    return a;
}
__device__ __forceinline__ void mbar_init(uint32_t mbar, uint32_t cnt) {
    asm volatile("mbarrier.init.shared.b64 [%0], %1;" :: "r"(mbar), "r"(cnt) : "memory");
}
__device__ __forceinline__ void mbar_expect_tx(uint32_t mbar, uint32_t bytes) {
    asm volatile("mbarrier.arrive.expect_tx.shared.b64 _, [%0], %1;"
                 :: "r"(mbar), "r"(bytes) : "memory");
}
__device__ __forceinline__ void mbar_wait(uint32_t mbar, uint32_t parity) {
    asm volatile(
        "{\n\t.reg .pred p;\n\t"
        "WAIT_%=:\n\t"
        "mbarrier.try_wait.parity.acquire.cta.shared::cta.b64 p, [%0], %1;\n\t"
        "@p bra.uni DONE_%=;\n\t"
        "bra.uni WAIT_%=;\n\t"
        "DONE_%=:\n\t}"
        :: "r"(mbar), "r"(parity) : "memory");
}
__device__ __forceinline__ void bulk_copy(uint32_t smem_dst, const void* gmem_src,
                                          uint32_t bytes, uint32_t mbar) {
    asm volatile(
        "cp.async.bulk.shared::cta.global.mbarrier::complete_tx::bytes [%0], [%1], %2, [%3];"
        :: "r"(smem_dst), "l"(gmem_src), "r"(bytes), "r"(mbar) : "memory");
}

// ---------------- k1a: one block per image-CHANNEL (R16, unchanged) ------------
__global__ void __launch_bounds__(NTHREADS) k1a_thresh(
    const float* __restrict__ rlab, const float* __restrict__ alab,
    const float* __restrict__ rpre, const float* __restrict__ apre,
    const float* __restrict__ mask, const int* __restrict__ neg_rto)
{
    const int ic  = blockIdx.x;
    const int img = ic & (NIMG - 1);
    const int ch  = ic >> 6;
    const float* __restrict__ lab = ch ? alab : rlab;
    const float* __restrict__ pre = ch ? apre : rpre;
    const size_t ibase = (size_t)img * NPIX;
    const int tid = threadIdx.x;
    const int ln  = tid & 31, w = tid >> 5;

    __shared__ int hist[NBINS];
    #pragma unroll
    for (int i = tid; i < NBINS; i += NTHREADS) hist[i] = 0;
    __syncthreads();

    int posc = 0;
    #pragma unroll
    for (int c = 0; c < 4; ++c) {
        const size_t off = ibase + (size_t)c * (NPIX / 4) + (size_t)tid * 4;
        float4 L = __ldcs((const float4*)(lab + off));
        float4 P = __ldcs((const float4*)(pre + off));
        float4 M = __ldcs((const float4*)(mask + off));

        #define SPROC(LL, PP, MM)                                      \
        {   float d = (PP) - (LL);                                     \
            float l = d * d * (MM);                                    \
            bool po = (LL) > POS_THR;                                  \
            posc += po ? 1 : 0;                                        \
            if (!po) {                                                 \
                int cc = __float2int_rz(sqrtf(l) * ((float)NBINS / 1.1f)); \
                atomicAdd(&hist[min(cc, NBINS - 1)], 1);               \
            } }
        SPROC(L.x, P.x, M.x)
        SPROC(L.y, P.y, M.y)
        SPROC(L.z, P.z, M.z)
        SPROC(L.w, P.w, M.w)
        #undef SPROC
    }

    __shared__ int shp[NTHREADS / 32];
    {
        int pw = warp_sum_i(posc);
        if (ln == 0) shp[w] = pw;
    }
    __syncthreads();
    __shared__ float s_j;
    __shared__ int s_total, s_bstar;
    __shared__ int wtot[NTHREADS / 32];
    if (tid == 0) {
        int ps = 0;
        #pragma unroll
        for (int i = 0; i < NTHREADS / 32; ++i) ps += shp[i];
        float peff_s = (ps > 0) ? (float)ps : (FALLBACK_POS / (float)SRATE);
        s_j = (float)(*neg_rto) * peff_s;
        s_bstar = NBINS - 1;
    }
    __syncthreads();

    int h0 = hist[4 * tid + 0];
    int h1 = hist[4 * tid + 1];
    int h2 = hist[4 * tid + 2];
    int h3 = hist[4 * tid + 3];
    int csum = h0 + h1 + h2 + h3;

    int x = csum;
    #pragma unroll
    for (int o = 1; o < 32; o <<= 1) {
        int y = __shfl_up_sync(0xffffffffu, x, o);
        if (ln >= o) x += y;
    }
    if (ln == 31) wtot[w] = x;
    __syncthreads();
    int woff = 0;
    #pragma unroll
    for (int i = 0; i < NTHREADS / 32; ++i) woff += (i < w) ? wtot[i] : 0;
    if (tid == 0) {
        int tot = 0;
        #pragma unroll
        for (int i = 0; i < NTHREADS / 32; ++i) tot += wtot[i];
        s_total = tot;
    }
    __syncthreads();

    {
        const int total = s_total;
        const float j = s_j;
        int run = (x - csum) + woff;   // exclusive prefix: sum of bins < 4*tid
        int b = -1;
        run += h0; if ((float)(total - run) <= j) { b = 4 * tid + 0; }
        if (b < 0) { run += h1; if ((float)(total - run) <= j) b = 4 * tid + 1; }
        if (b < 0) { run += h2; if ((float)(total - run) <= j) b = 4 * tid + 2; }
        if (b < 0) { run += h3; if ((float)(total - run) <= j) b = 4 * tid + 3; }
        if (b >= 0) atomicMin(&s_bstar, b);
    }
    __syncthreads();

    if (tid == 0) {
        const int b = s_bstar;
        const float t1 = ((float)(b + 1) * QBIN) * ((float)(b + 1) * QBIN);
        g_thr[ic] = t1;
        const int blo = max(b - 8, 0);
        const int bhi = min(b + 8, NBINS - 1);
        int wcnt = 0;
        for (int c = blo; c <= bhi; ++c) wcnt += hist[c];
        const float vlo = ((float)blo * QBIN) * ((float)blo * QBIN);
        const float vhi = ((float)(bhi + 1) * QBIN) * ((float)(bhi + 1) * QBIN);
        const float dv  = fmaxf(vhi - vlo, 1e-12f);
        g_rho[ic] = (wcnt > 0) ? ((float)SRATE * (float)wcnt / dv) : 3.4e38f;
    }
}

// ---------------- k1b: double-buffered bulk-async streaming pass (R15) ---------
__global__ void __launch_bounds__(NTHREADS) k1b_scan(
    const float* __restrict__ rlab, const float* __restrict__ alab,
    const float* __restrict__ rpre, const float* __restrict__ apre,
    const float* __restrict__ mask, const int* __restrict__ neg_rto,
    float* __restrict__ out)
{
    extern __shared__ __align__(128) unsigned char dsm[];
    __shared__ unsigned long long mbar_full[2];

    const int blk   = blockIdx.x;
    const int img   = blk / K1B_BPI;
    const int chunk = blk % K1B_BPI;
    const size_t pxbase = (size_t)img * NPIX + (size_t)chunk * BLK_PX;
    const int tid = threadIdx.x;
    const int w = tid >> 5, ln = tid & 31;

    const float* arrs[5];
    arrs[0] = rlab; arrs[1] = rpre; arrs[2] = alab; arrs[3] = apre; arrs[4] = mask;

    const uint32_t mb0 = smem_u32(&mbar_full[0]);
    const uint32_t mb1 = smem_u32(&mbar_full[1]);
    const uint32_t dbase = smem_u32(dsm);

    if (tid == 0) {
        mbar_init(mb0, 1);
        mbar_init(mb1, 1);
        asm volatile("fence.proxy.async;" ::: "memory");
    }
    __syncthreads();

    // prologue: fill both buffers
    if (tid == 0) {
        #pragma unroll
        for (int s = 0; s < 2; ++s) {
            const uint32_t mb = s ? mb1 : mb0;
            const uint32_t dst = dbase + s * STAGE_BYTES;
            mbar_expect_tx(mb, STAGE_BYTES);
            #pragma unroll
            for (int a = 0; a < 5; ++a) {
                const char* src = (const char*)arrs[a] +
                                  (pxbase + (size_t)s * STAGE_PX) * 4;
                bulk_copy(dst + a * STAGE_ARR_BYTES, src, STAGE_ARR_BYTES, mb);
            }
        }
    }

    const float t_r = g_thr[img];
    const float t_a = g_thr[NIMG + img];

    // packed int accumulators: p in bits[16:], C in bits[:16] (max 64 each/thread)
    int   pc_r = 0, pc_a = 0;
    float ps_r = 0.f, ts_r = 0.f, S_r = 0.f;
    float ps_a = 0.f, ts_a = 0.f, S_a = 0.f;

    for (int s = 0; s < NSTAGES; ++s) {
        const int b = s & 1;
        mbar_wait(b ? mb1 : mb0, (unsigned)((s >> 1) & 1));

        const float4* RL = (const float4*)(dsm + b * STAGE_BYTES + 0 * STAGE_ARR_BYTES);
        const float4* RP = (const float4*)(dsm + b * STAGE_BYTES + 1 * STAGE_ARR_BYTES);
        const float4* AL = (const float4*)(dsm + b * STAGE_BYTES + 2 * STAGE_ARR_BYTES);
        const float4* AP = (const float4*)(dsm + b * STAGE_BYTES + 3 * STAGE_ARR_BYTES);
        const float4* MK = (const float4*)(dsm + b * STAGE_BYTES + 4 * STAGE_ARR_BYTES);

        #pragma unroll
        for (int j = 0; j < 2; ++j) {
            const int u = tid + j * NTHREADS;    // 512 float4 per stage
            float4 rl = RL[u], rp = RP[u], al = AL[u], ap = AP[u], mk = MK[u];

            #define PROC(L, P, M, T, PC, PS, TS, SS)                   \
            {   float d = (P) - (L);                                   \
                float l = d * d * (M);                                 \
                TS += l;                                               \
                bool po = (L) > POS_THR;                               \
                PS += po ? l : 0.f;                                    \
                bool sel = (!po) && (l > (T));                         \
                SS += sel ? l : 0.f;                                   \
                PC += (po ? 0x10000 : 0) + (sel ? 1 : 0); }

            PROC(rl.x, rp.x, mk.x, t_r, pc_r, ps_r, ts_r, S_r)
            PROC(rl.y, rp.y, mk.y, t_r, pc_r, ps_r, ts_r, S_r)
            PROC(rl.z, rp.z, mk.z, t_r, pc_r, ps_r, ts_r, S_r)
            PROC(rl.w, rp.w, mk.w, t_r, pc_r, ps_r, ts_r, S_r)
            PROC(al.x, ap.x, mk.x, t_a, pc_a, ps_a, ts_a, S_a)
            PROC(al.y, ap.y, mk.y, t_a, pc_a, ps_a, ts_a, S_a)
            PROC(al.z, ap.z, mk.z, t_a, pc_a, ps_a, ts_a, S_a)
            PROC(al.w, ap.w, mk.w, t_a, pc_a, ps_a, ts_a, S_a)
            #undef PROC
        }

        __syncthreads();   // all consumers done with buffer b
        if (tid == 0 && s + 2 < NSTAGES) {
            const uint32_t mb = b ? mb1 : mb0;
            const uint32_t dst = dbase + b * STAGE_BYTES;
            mbar_expect_tx(mb, STAGE_BYTES);
            #pragma unroll
            for (int a = 0; a < 5; ++a) {
                const char* src = (const char*)arrs[a] +
                                  (pxbase + (size_t)(s + 2) * STAGE_PX) * 4;
                bulk_copy(dst + a * STAGE_ARR_BYTES, src, STAGE_ARR_BYTES, mb);
            }
        }
    }

    // block-reduce: 2 packed ints + 6 floats -> atomicAdd to 10 stat slots
    __shared__ int   shi[2][NTHREADS / 32];
    __shared__ float shf[6][NTHREADS / 32];
    {
        int iv[2] = {pc_r, pc_a};
        float fv[6] = {ps_r, ts_r, S_r, ps_a, ts_a, S_a};
        #pragma unroll
        for (int s = 0; s < 2; ++s) {
            int v = warp_sum_i(iv[s]);
            if (ln == 0) shi[s][w] = v;
        }
        #pragma unroll
        for (int s = 0; s < 6; ++s) {
            float v = warp_sum(fv[s]);
            if (ln == 0) shf[s][w] = v;
        }
    }
    __syncthreads();
    if (tid < 10) {
        const int ch = tid / 5;                    // 0: region, 1: affinity
        const int s  = tid % 5;                    // 0:p 1:ps 2:ts 3:S 4:C
        const int ic = img + ch * NIMG;
        float v;
        if (s == 0 || s == 4) {
            int tot = 0;
            #pragma unroll
            for (int i = 0; i < NTHREADS / 32; ++i) tot += shi[ch][i];
            v = (s == 0) ? (float)(tot >> 16) : (float)(tot & 0xffff);
        } else {
            const int f = ch * 3 + (s - 1);
            float t = 0.f;
            #pragma unroll
            for (int i = 0; i < NTHREADS / 32; ++i) t += shf[f][i];
            v = t;
        }
        float* tgt;
        switch (s) {
            case 0: tgt = &g_p [ic]; break;
            case 1: tgt = &g_ps[ic]; break;
            case 2: tgt = &g_ts[ic]; break;
            case 3: tgt = &g_S [ic]; break;
            default:tgt = &g_C [ic]; break;
        }
        atomicAdd(tgt, v);
    }

    // completion detection
    __shared__ unsigned s_rank;
    __syncthreads();
    if (tid == 0) {
        __threadfence();
        s_rank = atomicAdd(&g_done, 1u);
    }
    __syncthreads();
    if (s_rank != K1B_GRID - 1) return;

    // ===== completion block: assemble final scalar, re-zero state =====
    __threadfence();
    const int t = tid;
    float v = 0.f;
    if (t < NIC) {
        const float p   = *(volatile float*)&g_p[t];
        const float ps  = *(volatile float*)&g_ps[t];
        const float ts  = *(volatile float*)&g_ts[t];
        const float S   = *(volatile float*)&g_S[t];
        const float C   = *(volatile float*)&g_C[t];
        const float th  = g_thr[t];
        const float rho = g_rho[t];
        const float n   = (float)NPIX - p;

        const float pos_loss = (p > 0.f) ? ps / fmaxf(p, 1.f) : 0.f;
        const float peff = (p > 0.f) ? p : FALLBACK_POS;
        const float kf   = (float)(*neg_rto) * peff;
        const float k    = floorf(kf);

        float neg_loss;
        if ((p > 0.f) && (n < kf)) {
            neg_loss = (ts - ps) / fmaxf(n, 1.f);
        } else {
            // top-k sum with quadratic rank-error correction:
            //   sum = S + (k-C)*t - (k-C)^2 / (2*rho)
            const float dk   = k - C;
            const float corr = (rho > 0.f) ? (dk * dk) / (2.f * rho) : 0.f;
            const float topk = fmaxf(S + dk * th - corr, 0.f);
            neg_loss = topk / kf;
        }
        v = pos_loss + neg_loss;

        // re-zero all consumed accumulators for the next invocation / replay
        g_p[t] = 0.f; g_ps[t] = 0.f; g_ts[t] = 0.f;
        g_S[t] = 0.f; g_C[t]  = 0.f;
    }
    if (t == 0) g_done = 0u;

    float* red = (float*)dsm;   // reuse pipeline smem for the final reduction
    if (t < NIC) red[t] = v;
    __syncthreads();
    #pragma unroll
    for (int o = NIC / 2; o >= 1; o >>= 1) {
        if (t < o) red[t] += red[t + o];
        __syncthreads();
    }
    if (t == 0) out[0] = red[0] / (float)NIMG;
}

// ---------------- launch ----------------
extern "C" void kernel_launch(void* const* d_in, const int* in_sizes, int n_in,
                              void* d_out, int out_size)
{
    const float* rlab = (const float*)d_in[0];
    const float* alab = (const float*)d_in[1];
    const float* rpre = (const float*)d_in[2];
    const float* apre = (const float*)d_in[3];
    const float* mask = (const float*)d_in[4];
    const int*   nrto = (const int*)  d_in[5];
    float* out = (float*)d_out;
    (void)in_sizes; (void)n_in; (void)out_size;

    cudaFuncSetAttribute(k1b_scan, cudaFuncAttributeMaxDynamicSharedMemorySize, DYN_SMEM);

    k1a_thresh<<<NIC, NTHREADS>>>(rlab, alab, rpre, apre, mask, nrto);
    k1b_scan  <<<K1B_GRID, NTHREADS, DYN_SMEM>>>(rlab, alab, rpre, apre, mask, nrto, out);
}